// round 14
// baseline (speedup 1.0000x reference)
#include <cuda_runtime.h>
#include <cuda_fp16.h>
#include <math.h>
#include <stdint.h>

// Problem constants: B=4, K=64, L=128, D=768
#define NBK   256
#define LL    128
#define DD    768
#define NROWS 65536
#define NOUT  32768

#define ASTRH 40    // fp16 smem row stride (80 B), ldmatrix conflict-free

// Scratch
__device__ int    g_arg[NOUT];
__device__ float  g_y[NROWS];
__device__ __half g_w1h[DD * DD];            // w1^T fp16 [e][d]
__device__ __half g_xh[(size_t)NROWS * DD];  // normalized rows, fp16 hi
__device__ __half g_xl[(size_t)NROWS * DD];  // normalized rows, fp16 lo residual

__device__ __forceinline__ void ldsm_x4(uint32_t* r, uint32_t addr) {
    asm volatile("ldmatrix.sync.aligned.m8n8.x4.shared.b16 {%0,%1,%2,%3}, [%4];"
        : "=r"(r[0]), "=r"(r[1]), "=r"(r[2]), "=r"(r[3]) : "r"(addr));
}
__device__ __forceinline__ void mma_fp16(float* d, const uint32_t* a, const uint32_t* b) {
    asm volatile(
        "mma.sync.aligned.m16n8k16.row.col.f32.f16.f16.f32 "
        "{%0,%1,%2,%3}, {%4,%5,%6,%7}, {%8,%9}, {%0,%1,%2,%3};"
        : "+f"(d[0]), "+f"(d[1]), "+f"(d[2]), "+f"(d[3])
        : "r"(a[0]), "r"(a[1]), "r"(a[2]), "r"(a[3]), "r"(b[0]), "r"(b[1]));
}
__device__ __forceinline__ uint32_t smem_u32(const void* p) {
    uint32_t a;
    asm("{ .reg .u64 t; cvta.to.shared.u64 t, %1; cvt.u32.u64 %0, t; }" : "=r"(a) : "l"(p));
    return a;
}
__device__ __forceinline__ uint32_t pack2(float x, float y) {
    __half2 h = __floats2half2_rn(x, y);
    return *reinterpret_cast<uint32_t*>(&h);
}
#define CP16(dst, src) \
    asm volatile("cp.async.cg.shared.global [%0], [%1], 16;" :: "r"(dst), "l"(src))
#define CP_COMMIT() asm volatile("cp.async.commit_group;" ::: "memory")
#define CP_WAIT(n)  asm volatile("cp.async.wait_group %0;" :: "n"(n) : "memory")

// ---------------------------------------------------------------------------
// Kernel A: normalized-fp16 X, split hi + lo residual (one warp per row)
// ---------------------------------------------------------------------------
__global__ void prep_x_kernel(const float* __restrict__ x) {
    int row  = blockIdx.x * 8 + (threadIdx.x >> 5);
    int lane = threadIdx.x & 31;
    const float4* p = reinterpret_cast<const float4*>(x) + (size_t)row * (DD / 4);
    float4 v[6];
    float s = 0.f;
    #pragma unroll
    for (int i = 0; i < 6; i++) {
        v[i] = p[lane + i * 32];
        s += v[i].x * v[i].x + v[i].y * v[i].y + v[i].z * v[i].z + v[i].w * v[i].w;
    }
    #pragma unroll
    for (int o = 16; o; o >>= 1) s += __shfl_xor_sync(0xffffffffu, s, o);
    float inv = 1.0f / sqrtf(s);
    uint2* dh = reinterpret_cast<uint2*>(g_xh + (size_t)row * DD);
    uint2* dl = reinterpret_cast<uint2*>(g_xl + (size_t)row * DD);
    #pragma unroll
    for (int i = 0; i < 6; i++) {
        float n0 = v[i].x * inv, n1 = v[i].y * inv;
        float n2 = v[i].z * inv, n3 = v[i].w * inv;
        __half h0 = __float2half_rn(n0), h1 = __float2half_rn(n1);
        __half h2 = __float2half_rn(n2), h3 = __float2half_rn(n3);
        uint2 uh, ul;
        __half2 hh01 = __halves2half2(h0, h1);
        __half2 hh23 = __halves2half2(h2, h3);
        uh.x = *reinterpret_cast<uint32_t*>(&hh01);
        uh.y = *reinterpret_cast<uint32_t*>(&hh23);
        ul.x = pack2(n0 - __half2float(h0), n1 - __half2float(h1));
        ul.y = pack2(n2 - __half2float(h2), n3 - __half2float(h3));
        dh[lane + i * 32] = uh;
        dl[lane + i * 32] = ul;
    }
}

// ---------------------------------------------------------------------------
// Kernel B: w1 -> fp16, transposed to [e][d]
// ---------------------------------------------------------------------------
__global__ void prep_w1_kernel(const float* __restrict__ w1) {
    int e = blockIdx.x;
    for (int d = threadIdx.x; d < DD; d += 256)
        g_w1h[e * DD + d] = __float2half_rn(__ldg(w1 + (size_t)d * DD + e));
}

// ---------------------------------------------------------------------------
// MLP kernel (R13, validated 250.8us): 128x128 tiles, 6 e-passes, KC=64,
// cp.async double-buffered; 8 warps = 4(M) x 2(N), warp tile 32x64.
// ---------------------------------------------------------------------------
#define KC     64
#define ASTR2  72
#define ABYTES (128 * ASTR2 * 2)
#define M_AS   0
#define M_BS   36864
#define M_SRED 73728
#define MLP_SMEM 74752

__global__ __launch_bounds__(256, 2) void mlp_kernel(const float* __restrict__ b1,
                                                     const float* __restrict__ w2,
                                                     const float* __restrict__ b2) {
    extern __shared__ char smem[];
    float* sred = reinterpret_cast<float*>(smem + M_SRED);
    uint32_t as_u32 = smem_u32(smem) + M_AS;
    uint32_t bs_u32 = smem_u32(smem) + M_BS;

    int rt = blockIdx.x;
    const __half* Xh = g_xh + (size_t)rt * LL * DD;

    int t    = threadIdx.x;
    int lane = t & 31;
    int wid  = t >> 5;
    int wm   = wid & 3;
    int wn   = wid >> 2;
    int lq   = lane >> 2;
    int lr   = lane & 3;

    int srow[4], sc16[4];
    #pragma unroll
    for (int it = 0; it < 4; it++) {
        int idx = t + it * 256;
        srow[it] = idx >> 3;
        sc16[it] = idx & 7;
    }

    uint32_t a_frag_base = as_u32 +
        (uint32_t)(((wm * 32 + (lane & 15)) * ASTR2 + (lane >> 4) * 8) * 2);
    uint32_t b_row_off = ((lane >> 4) * 8 + (lane & 7));
    uint32_t b_k_off   = ((lane >> 3) & 1) * 8;
    uint32_t b_frag_base = bs_u32 +
        (uint32_t)(((wn * 64 + b_row_off) * ASTR2 + b_k_off) * 2);

    float yacc[4] = {0.f, 0.f, 0.f, 0.f};

    for (int ec = 0; ec < 6; ec++) {
        float acc[2][8][4];
        #pragma unroll
        for (int mi = 0; mi < 2; mi++)
            #pragma unroll
            for (int ni = 0; ni < 8; ni++)
                #pragma unroll
                for (int c = 0; c < 4; c++) acc[mi][ni][c] = 0.f;

        auto issue = [&](int cidx, int buf) {
            int d0 = cidx * KC;
            #pragma unroll
            for (int it = 0; it < 4; it++) {
                uint32_t soff = (uint32_t)((srow[it] * ASTR2 + sc16[it] * 8) * 2)
                              + (uint32_t)buf * ABYTES;
                CP16(as_u32 + soff, Xh + (size_t)srow[it] * DD + d0 + sc16[it] * 8);
                CP16(bs_u32 + soff,
                     g_w1h + (size_t)(ec * 128 + srow[it]) * DD + d0 + sc16[it] * 8);
            }
        };

        issue(0, 0);
        CP_COMMIT();

        for (int c = 0; c < 12; c++) {
            int buf = c & 1;
            if (c < 11) {
                issue(c + 1, buf ^ 1);
                CP_COMMIT();
                CP_WAIT(1);
            } else {
                CP_WAIT(0);
            }
            __syncthreads();

            uint32_t abase = a_frag_base + buf * ABYTES;
            uint32_t bbase = b_frag_base + buf * ABYTES;
            #pragma unroll
            for (int kk = 0; kk < 4; kk++) {
                uint32_t a[2][4];
                #pragma unroll
                for (int mi = 0; mi < 2; mi++)
                    ldsm_x4(a[mi], abase + mi * (16 * ASTR2 * 2) + kk * 32);
                uint32_t b[4][4];
                #pragma unroll
                for (int nb = 0; nb < 4; nb++)
                    ldsm_x4(b[nb], bbase + nb * (16 * ASTR2 * 2) + kk * 32);
                #pragma unroll
                for (int mi = 0; mi < 2; mi++)
                    #pragma unroll
                    for (int nb = 0; nb < 4; nb++) {
                        mma_fp16(acc[mi][nb * 2 + 0], a[mi], &b[nb][0]);
                        mma_fp16(acc[mi][nb * 2 + 1], a[mi], &b[nb][2]);
                    }
            }
            __syncthreads();
        }

        #pragma unroll
        for (int ni = 0; ni < 8; ni++) {
            int e0 = ec * 128 + wn * 64 + ni * 8 + lr * 2;
            float b1a = __ldg(b1 + e0),     b1b = __ldg(b1 + e0 + 1);
            float w2a = __ldg(w2 + e0),     w2b = __ldg(w2 + e0 + 1);
            #pragma unroll
            for (int mi = 0; mi < 2; mi++) {
                float h;
                h = acc[mi][ni][0] + b1a; if (h > 0.f) yacc[mi * 2 + 0] += h * w2a;
                h = acc[mi][ni][1] + b1b; if (h > 0.f) yacc[mi * 2 + 0] += h * w2b;
                h = acc[mi][ni][2] + b1a; if (h > 0.f) yacc[mi * 2 + 1] += h * w2a;
                h = acc[mi][ni][3] + b1b; if (h > 0.f) yacc[mi * 2 + 1] += h * w2b;
            }
        }
    }

    #pragma unroll
    for (int j = 0; j < 4; j++) {
        yacc[j] += __shfl_xor_sync(0xffffffffu, yacc[j], 1);
        yacc[j] += __shfl_xor_sync(0xffffffffu, yacc[j], 2);
    }
    if (lr == 0) {
        #pragma unroll
        for (int j = 0; j < 4; j++) {
            int row = wm * 32 + (j >> 1) * 16 + (j & 1) * 8 + lq;
            sred[row * 2 + wn] = yacc[j];
        }
    }
    __syncthreads();
    if (t < 128)
        g_y[rt * LL + t] = sred[t * 2] + sred[t * 2 + 1] + __ldg(b2);
}

// ---------------------------------------------------------------------------
// Scores kernel: cosine directly on precomputed normalized split (hh+lh+hl),
// all tiles via cp.async; no divisions in epilogue. 64 ctx x 128 ent per
// block (512 blocks), KC=32; 8 warps = 2(M) x 4(N), warp tile 32x32.
// ---------------------------------------------------------------------------
#define SBUF   30720                // bytes per buffer (AH+AL+BH+BL)
#define S_AH   0                    // 64*40*2  = 5120
#define S_AL   5120
#define S_BH   10240                // 128*40*2 = 10240
#define S_BL   20480
#define S_RV   61440                // 256 f32
#define S_RI   62464                // 256 i32
#define SC_SMEM 63488

__global__ __launch_bounds__(256, 2) void scores_kernel() {
    extern __shared__ char smem[];
    uint32_t sb = smem_u32(smem);
    float* rv = reinterpret_cast<float*>(smem + S_RV);
    int*   ri = reinterpret_cast<int*>(smem + S_RI);

    int sid = blockIdx.x;
    int bk = sid >> 1;
    int lo = (sid & 1) * 64;
    const __half* ctx_h = g_xh + ((size_t)(bk * 2) * LL + lo) * DD;
    const __half* ctx_l = g_xl + ((size_t)(bk * 2) * LL + lo) * DD;
    const __half* ent_h = g_xh + (size_t)(bk * 2 + 1) * LL * DD;
    const __half* ent_l = g_xl + (size_t)(bk * 2 + 1) * LL * DD;

    int t    = threadIdx.x;
    int lane = t & 31;
    int wid  = t >> 5;
    int wm   = wid & 1;
    int wn   = wid >> 1;
    int lq   = lane >> 2;
    int lr   = lane & 3;

    // cp.async geometry: 16B segs; A tiles 64x4 segs (1/thread each),
    // B tiles 128x4 segs (2/thread each)
    int ar = t >> 2, as_ = t & 3;
    int br[2], bs_[2];
    #pragma unroll
    for (int it = 0; it < 2; it++) {
        int idx = t + it * 256;
        br[it] = idx >> 2;  bs_[it] = idx & 3;
    }

    uint32_t frag_a = (uint32_t)(((wm * 32 + (lane & 15)) * ASTRH + (lane >> 4) * 8) * 2);
    uint32_t b_row_off = ((lane >> 4) * 8 + (lane & 7));
    uint32_t b_k_off   = ((lane >> 3) & 1) * 8;
    uint32_t frag_b = (uint32_t)(((wn * 32 + b_row_off) * ASTRH + b_k_off) * 2);

    float acc[2][4][4];
    #pragma unroll
    for (int mi = 0; mi < 2; mi++)
        #pragma unroll
        for (int ni = 0; ni < 4; ni++)
            #pragma unroll
            for (int c = 0; c < 4; c++) acc[mi][ni][c] = 0.f;

    auto issue = [&](int cidx, int buf) {
        int d0 = cidx * 32;
        uint32_t bb = sb + (uint32_t)buf * SBUF;
        uint32_t aoff = (uint32_t)((ar * ASTRH + as_ * 8) * 2);
        CP16(bb + S_AH + aoff, ctx_h + (size_t)ar * DD + d0 + as_ * 8);
        CP16(bb + S_AL + aoff, ctx_l + (size_t)ar * DD + d0 + as_ * 8);
        #pragma unroll
        for (int it = 0; it < 2; it++) {
            uint32_t boff = (uint32_t)((br[it] * ASTRH + bs_[it] * 8) * 2);
            CP16(bb + S_BH + boff, ent_h + (size_t)br[it] * DD + d0 + bs_[it] * 8);
            CP16(bb + S_BL + boff, ent_l + (size_t)br[it] * DD + d0 + bs_[it] * 8);
        }
    };

    issue(0, 0);
    CP_COMMIT();

    for (int c = 0; c < 24; c++) {
        int buf = c & 1;
        if (c < 23) {
            issue(c + 1, buf ^ 1);
            CP_COMMIT();
            CP_WAIT(1);
        } else {
            CP_WAIT(0);
        }
        __syncthreads();

        uint32_t bb = sb + (uint32_t)buf * SBUF;
        uint32_t ah_base = bb + S_AH + frag_a;
        uint32_t al_base = bb + S_AL + frag_a;
        uint32_t bh_base = bb + S_BH + frag_b;
        uint32_t bl_base = bb + S_BL + frag_b;
        #pragma unroll
        for (int kk = 0; kk < 2; kk++) {
            uint32_t ah[2][4], al[2][4];
            #pragma unroll
            for (int mi = 0; mi < 2; mi++) {
                ldsm_x4(ah[mi], ah_base + mi * (16 * ASTRH * 2) + kk * 32);
                ldsm_x4(al[mi], al_base + mi * (16 * ASTRH * 2) + kk * 32);
            }
            #pragma unroll
            for (int nb = 0; nb < 2; nb++) {
                uint32_t bh[4];
                ldsm_x4(bh, bh_base + nb * (16 * ASTRH * 2) + kk * 32);
                #pragma unroll
                for (int mi = 0; mi < 2; mi++) {
                    mma_fp16(acc[mi][nb * 2 + 0], ah[mi], &bh[0]);
                    mma_fp16(acc[mi][nb * 2 + 1], ah[mi], &bh[2]);
                    mma_fp16(acc[mi][nb * 2 + 0], al[mi], &bh[0]);
                    mma_fp16(acc[mi][nb * 2 + 1], al[mi], &bh[2]);
                }
                uint32_t bl[4];
                ldsm_x4(bl, bl_base + nb * (16 * ASTRH * 2) + kk * 32);
                #pragma unroll
                for (int mi = 0; mi < 2; mi++) {
                    mma_fp16(acc[mi][nb * 2 + 0], ah[mi], &bl[0]);
                    mma_fp16(acc[mi][nb * 2 + 1], ah[mi], &bl[2]);
                }
            }
        }
        __syncthreads();
    }

    // argmax on accumulators (acc == cosine); first-index tie-break
    float bv[4];
    int   bi4[4];
    #pragma unroll
    for (int s = 0; s < 4; s++) { bv[s] = -3.4e38f; bi4[s] = 0; }
    #pragma unroll
    for (int ni = 0; ni < 4; ni++) {
        int col0 = wn * 32 + ni * 8 + lr * 2;
        #pragma unroll
        for (int mi = 0; mi < 2; mi++) {
            if (acc[mi][ni][0] > bv[mi * 2]) { bv[mi * 2] = acc[mi][ni][0]; bi4[mi * 2] = col0; }
            if (acc[mi][ni][1] > bv[mi * 2]) { bv[mi * 2] = acc[mi][ni][1]; bi4[mi * 2] = col0 + 1; }
            if (acc[mi][ni][2] > bv[mi * 2 + 1]) { bv[mi * 2 + 1] = acc[mi][ni][2]; bi4[mi * 2 + 1] = col0; }
            if (acc[mi][ni][3] > bv[mi * 2 + 1]) { bv[mi * 2 + 1] = acc[mi][ni][3]; bi4[mi * 2 + 1] = col0 + 1; }
        }
    }
    #pragma unroll
    for (int s = 0; s < 4; s++) {
        #pragma unroll
        for (int o = 1; o <= 2; o <<= 1) {
            float ov = __shfl_xor_sync(0xffffffffu, bv[s], o);
            int   oi = __shfl_xor_sync(0xffffffffu, bi4[s], o);
            if (ov > bv[s] || (ov == bv[s] && oi < bi4[s])) { bv[s] = ov; bi4[s] = oi; }
        }
    }
    if (lr == 0) {
        #pragma unroll
        for (int s = 0; s < 4; s++) {
            int row = wm * 32 + (s >> 1) * 16 + (s & 1) * 8 + lq;
            rv[row * 4 + wn] = bv[s];
            ri[row * 4 + wn] = bi4[s];
        }
    }
    __syncthreads();
    if (t < 64) {
        float best = rv[t * 4]; int bi = ri[t * 4];
        #pragma unroll
        for (int j = 1; j < 4; j++) {
            float v = rv[t * 4 + j];
            int   i = ri[t * 4 + j];
            if (v > best || (v == best && i < bi)) { best = v; bi = i; }
        }
        g_arg[bk * LL + lo + t] = bi;
    }
}

// ---------------------------------------------------------------------------
// Kernel C: out = y_ctx + y_ent[argmax]
// ---------------------------------------------------------------------------
__global__ void finalize_kernel(float* __restrict__ out) {
    int i  = blockIdx.x * 256 + threadIdx.x;
    int bk = i >> 7;
    float yc = g_y[(bk * 2) * LL + (i & 127)];
    float ye = g_y[(bk * 2 + 1) * LL + g_arg[i]];
    out[i] = yc + ye;
}

extern "C" void kernel_launch(void* const* d_in, const int* in_sizes, int n_in,
                              void* d_out, int out_size) {
    const float* context = (const float*)d_in[0];
    const float* w1      = (const float*)d_in[1];
    const float* b1      = (const float*)d_in[2];
    const float* w2      = (const float*)d_in[3];
    const float* b2      = (const float*)d_in[4];
    float* out = (float*)d_out;

    cudaFuncSetAttribute(mlp_kernel,
                         cudaFuncAttributeMaxDynamicSharedMemorySize, MLP_SMEM);
    cudaFuncSetAttribute(scores_kernel,
                         cudaFuncAttributeMaxDynamicSharedMemorySize, SC_SMEM);

    prep_w1_kernel<<<DD, 256>>>(w1);
    prep_x_kernel<<<NROWS / 8, 256>>>(context);
    scores_kernel<<<512, 256, SC_SMEM>>>();
    mlp_kernel<<<NROWS / 128, 256, MLP_SMEM>>>(b1, w2, b2);
    finalize_kernel<<<NOUT / 256, 256>>>(out);
}